// round 16
// baseline (speedup 1.0000x reference)
#include <cuda_runtime.h>
#include <cuda_fp16.h>
#include <cstdint>

typedef unsigned long long ull;

#define BB 2048
#define SS 512
#define NROW (BB * SS)
#define G3 96
#define HID 32
#define INSZ 64

// -------- device scratch --------
__device__ __half g_gx[(size_t)NROW * G3];  // fp16 input-part gates (+b_ih), 201MB
__device__ ull    g_Gp[16 * 32];
__device__ float  g_d[32];
__device__ float  g_gv[32];
__device__ float  g_f[1];
__device__ float  g_H[32 * 2];
__device__ float  g_e[2];

// -------- helpers --------
__device__ __forceinline__ void ffma2(ull& d, ull a, ull b) {
    asm("fma.rn.f32x2 %0, %1, %2, %0;" : "+l"(d) : "l"(a), "l"(b));
}
__device__ __forceinline__ ull pack2(float a, float b) {
    ull r; asm("mov.b64 %0, {%1, %2};" : "=l"(r) : "f"(a), "f"(b)); return r;
}
__device__ __forceinline__ float hsum(ull v) {
    return __uint_as_float((unsigned)v) + __uint_as_float((unsigned)(v >> 32));
}
__device__ __forceinline__ float wsum(float v) {
#pragma unroll
    for (int o = 16; o; o >>= 1) v += __shfl_xor_sync(0xffffffffu, v, o);
    return v;
}
__device__ __forceinline__ float sigmoidf_(float x) {
    return __fdividef(1.f, 1.f + __expf(-x));
}
__device__ __forceinline__ float tanhf_(float x) {
    return 1.f - __fdividef(2.f, __expf(2.f * x) + 1.f);
}

// ============================================================================
// Phase 0: precompute folded memory matrices
// ============================================================================
__global__ void precompute_kernel(
    const float* __restrict__ Wk, const float* __restrict__ bk,
    const float* __restrict__ Wq, const float* __restrict__ bq,
    const float* __restrict__ Wv, const float* __restrict__ bv,
    const float* __restrict__ Wr)
{
    __shared__ float Gs[32 * 32];
    int tid = threadIdx.x;
    {
        int i = tid >> 5, j = tid & 31;
        float s = 0.f;
        for (int k = 0; k < 64; ++k) s += Wk[k * 32 + i] * Wq[k * 32 + j];
        Gs[i * 32 + j] = s;
    }
    if (tid < 32) {
        float dv = 0.f, gv = 0.f;
        for (int k = 0; k < 64; ++k) {
            dv += bk[k] * Wq[k * 32 + tid];
            gv += Wk[k * 32 + tid] * bq[k];
        }
        g_d[tid] = dv; g_gv[tid] = gv;
    }
    if (tid == 0) {
        float f = 0.f;
        for (int k = 0; k < 64; ++k) f += bk[k] * bq[k];
        g_f[0] = f;
    }
    if (tid < 64) {
        int i = tid >> 1, r = tid & 1;
        float s = 0.f;
        for (int v = 0; v < 64; ++v) s += Wv[v * 32 + i] * Wr[r * 64 + v];
        g_H[i * 2 + r] = s;
    }
    if (tid < 2) {
        float s = 0.f;
        for (int v = 0; v < 64; ++v) s += bv[v] * Wr[tid * 64 + v];
        g_e[tid] = s;
    }
    __syncthreads();
    if (tid < 512) {
        int k = tid >> 5, j = tid & 31;
        g_Gp[tid] = pack2(Gs[(2 * k) * 32 + j], Gs[(2 * k + 1) * 32 + j]);
    }
}

// ============================================================================
// Phase 1: GX[row][96] = inputs[row][0:64] @ w_ih[:, :64].T + b_ih  (fp16 out)
// ============================================================================
__global__ __launch_bounds__(128) void phase1_kernel(
    const float* __restrict__ xin,
    const float* __restrict__ w_ih,
    const float* __restrict__ b_ih)
{
    __shared__ __align__(16) ulonglong2 w4s[16 * 96];
    __shared__ __align__(16) ulonglong2 xb[4][128];

    const int tid = threadIdx.x;
    const int w = tid >> 5, lane = tid & 31;

    for (int idx = tid; idx < 16 * 96; idx += 128) {
        int kq = idx / 96, j = idx % 96;
        const float* p = w_ih + j * 66 + kq * 4;
        ulonglong2 v; v.x = pack2(p[0], p[1]); v.y = pack2(p[2], p[3]);
        w4s[idx] = v;
    }
    const float b0 = b_ih[lane], b1 = b_ih[lane + 32], b2 = b_ih[lane + 64];
    __syncthreads();

    const int blockRow0 = blockIdx.x * 256;
    for (int tile = 0; tile < 8; ++tile) {
        const int rowBase = blockRow0 + tile * 32 + w * 8;
        const ulonglong2* src = (const ulonglong2*)(xin + (size_t)rowBase * INSZ);
        __syncwarp();
#pragma unroll
        for (int i = 0; i < 4; ++i) xb[w][lane + 32 * i] = src[lane + 32 * i];
        __syncwarp();

        ull acc[8][3];
#pragma unroll
        for (int r = 0; r < 8; ++r) { acc[r][0] = 0; acc[r][1] = 0; acc[r][2] = 0; }

#pragma unroll
        for (int kq = 0; kq < 16; ++kq) {
            ulonglong2 w0 = w4s[kq * 96 + lane];
            ulonglong2 w1 = w4s[kq * 96 + lane + 32];
            ulonglong2 w2 = w4s[kq * 96 + lane + 64];
#pragma unroll
            for (int r = 0; r < 8; ++r) {
                ulonglong2 xv = xb[w][r * 16 + kq];
                ffma2(acc[r][0], xv.x, w0.x); ffma2(acc[r][0], xv.y, w0.y);
                ffma2(acc[r][1], xv.x, w1.x); ffma2(acc[r][1], xv.y, w1.y);
                ffma2(acc[r][2], xv.x, w2.x); ffma2(acc[r][2], xv.y, w2.y);
            }
        }
#pragma unroll
        for (int r = 0; r < 8; ++r) {
            __half* o = g_gx + (size_t)(rowBase + r) * G3;
            o[lane]      = __float2half_rn(hsum(acc[r][0]) + b0);
            o[lane + 32] = __float2half_rn(hsum(acc[r][1]) + b1);
            o[lane + 64] = __float2half_rn(hsum(acc[r][2]) + b2);
        }
    }
}

// ============================================================================
// Phase 2: sequential scan. 128-thread blocks = 4 warps = 4 batch elements,
// so warps map to ALL FOUR SMSPs (wid%4). grid 512, occupancy 4.
// ============================================================================
__global__ __launch_bounds__(128, 4) void phase2_kernel(
    const float* __restrict__ w_ih,
    const float* __restrict__ w_hh,
    const float* __restrict__ b_hh,
    const float* __restrict__ b_recall,
    float* __restrict__ hid)
{
    __shared__ __align__(16) float hbuf[4][3][32];   // [warp][slot][lane]
    __shared__ __align__(16) ull whh2s[16][33];      // n-gate weights, padded
    __shared__ __align__(16) ulonglong2 As2[4][8][4];// [warp][k2][m] packed A quads
    __shared__ float tmpA[4][3][32];

    const int tid = threadIdx.x;
    const int w = tid >> 5, lane = tid & 31;
    const int b = blockIdx.x * 4 + w;

    for (int idx = tid; idx < 512; idx += 128) {
        int k = idx >> 5, l = idx & 31;
        whh2s[k][l] = pack2(w_hh[(l + 64) * 32 + 2 * k],
                            w_hh[(l + 64) * 32 + 2 * k + 1]);
    }

    ull whh0[16], whh1[16];
    {
        const ulonglong2* p0 = (const ulonglong2*)(w_hh + (size_t)lane * 32);
        const ulonglong2* p1 = (const ulonglong2*)(w_hh + (size_t)(lane + 32) * 32);
#pragma unroll
        for (int i = 0; i < 8; ++i) {
            ulonglong2 v;
            v = p0[i]; whh0[2 * i] = v.x; whh0[2 * i + 1] = v.y;
            v = p1[i]; whh1[2 * i] = v.x; whh1[2 * i + 1] = v.y;
        }
    }
    __syncthreads();

    const float wr00 = w_ih[lane * 66 + 64],        wr01 = w_ih[lane * 66 + 65];
    const float wr10 = w_ih[(lane + 32) * 66 + 64], wr11 = w_ih[(lane + 32) * 66 + 65];
    const float wr20 = w_ih[(lane + 64) * 66 + 64], wr21 = w_ih[(lane + 64) * 66 + 65];
    const float bh0 = b_hh[lane], bh1 = b_hh[lane + 32], bh2 = b_hh[lane + 64];
    const float br0 = b_recall[0], br1 = b_recall[1];

    float A0o = 0.f, A1o = 0.f, A2o = 0.f;
    float c0 = 0.f, c1 = 0.f, c2 = 0.f;
    float R00 = 0.f, R01 = 0.f, R10 = 0.f, R11 = 0.f, R20 = 0.f, R21 = 0.f;
    float retr0 = 0.f, retr1 = 0.f, h_own = 0.f;

    const __half* gxp = g_gx + (size_t)b * SS * G3;
    float* hrow = hid + (size_t)b * SS * HID + lane;
    float gx0 = __half2float(gxp[lane]);
    float gx1 = __half2float(gxp[lane + 32]);
    float gx2 = __half2float(gxp[lane + 64]);
    ull* hb2 = (ull*)hbuf[w][2];

    // ---------- prologue: t = 0..3 ----------
    {
        const float dj = g_d[lane], g_own = g_gv[lane];
        const float H0o = g_H[lane * 2], H1o = g_H[lane * 2 + 1];
        const float fv = g_f[0], e0c = g_e[0], e1c = g_e[1];
#pragma unroll
        for (int t = 0; t < 4; ++t) {
            float gxr = fmaf(retr1, wr01, fmaf(retr0, wr00, gx0));
            float gxz = fmaf(retr1, wr11, fmaf(retr0, wr10, gx1));
            float gxn = fmaf(retr1, wr21, fmaf(retr0, wr20, gx2));
            const __half* q = gxp + (size_t)(t + 1) * G3;
            gx0 = __half2float(q[lane]);
            gx1 = __half2float(q[lane + 32]);
            gx2 = __half2float(q[lane + 64]);

            hbuf[w][2][lane] = h_own; __syncwarp();
            ull ar = 0, az = 0, an = 0;
#pragma unroll
            for (int k = 0; k < 16; ++k) {
                ull hp = hb2[k];
                ffma2(ar, hp, whh0[k]);
                ffma2(az, hp, whh1[k]);
                ffma2(an, hp, whh2s[k][lane]);
            }
            __syncwarp();
            float ghr = hsum(ar) + bh0, ghz = hsum(az) + bh1, ghn = hsum(an) + bh2;
            float r = sigmoidf_(gxr + ghr);
            float z = sigmoidf_(gxz + ghz);
            float n = tanhf_(fmaf(r, ghn, gxn));
            float h_new = (t == 3) ? 0.f : fmaf(z, h_own - n, n);

            if (t < 3) {
                hbuf[w][2][lane] = h_new; __syncwarp();
                ull aa = 0;
#pragma unroll
                for (int k = 0; k < 16; ++k) ffma2(aa, hb2[k], g_Gp[k * 32 + lane]);
                __syncwarp();
                float Av  = hsum(aa) + dj;
                float cv  = wsum(h_new * g_own) + fv;
                float Rv0 = wsum(h_new * H0o) + e0c;
                float Rv1 = wsum(h_new * H1o) + e1c;
                if (t == 0)      { A0o = Av; c0 = cv; R00 = Rv0; R01 = Rv1; }
                else if (t == 1) { A1o = Av; c1 = cv; R10 = Rv0; R11 = Rv1; }
                else             { A2o = Av; c2 = cv; R20 = Rv0; R21 = Rv1; }
            }
            float s0 = wsum(h_new * A0o) + c0;
            float s1 = wsum(h_new * A1o) + c1;
            float s2 = wsum(h_new * A2o) + c2;
            int counter = (t < 3) ? t : 3;
            float m0 = (0 < counter) ? s0 : -1e30f;
            float m1 = (1 < counter) ? s1 : -1e30f;
            float m2 = (2 < counter) ? s2 : -1e30f;
            float p0 = __expf(m0), p1 = __expf(m1), p2 = __expf(m2);
            float inv = __fdividef(1.f, p0 + p1 + p2);
            float nr0 = fmaf(p2, R20, fmaf(p1, R10, p0 * R00)) * inv + br0;
            float nr1 = fmaf(p2, R21, fmaf(p1, R11, p0 * R01)) * inv + br1;
            retr0 = (t > 0) ? nr0 : 0.f;
            retr1 = (t > 0) ? nr1 : 0.f;
            hrow[(size_t)t * HID] = h_new;
            h_own = h_new;
        }
    }

    // pack A columns into smem as ulonglong2 quads for the in-matvec score rows
    tmpA[w][0][lane] = A0o; tmpA[w][1][lane] = A1o; tmpA[w][2][lane] = A2o;
    __syncwarp();
    if (lane < 8) {
#pragma unroll
        for (int m = 0; m < 3; ++m) {
            ulonglong2 v;
            v.x = pack2(tmpA[w][m][4 * lane],     tmpA[w][m][4 * lane + 1]);
            v.y = pack2(tmpA[w][m][4 * lane + 2], tmpA[w][m][4 * lane + 3]);
            As2[w][lane][m] = v;
        }
    }
    const float cA = (lane == 0) ? c0 : ((lane == 1) ? c1 : ((lane == 2) ? c2 : 0.f));
    const float RWr0 = fmaf(R01, wr01, R00 * wr00);
    const float RWr1 = fmaf(R11, wr01, R10 * wr00);
    const float RWr2 = fmaf(R21, wr01, R20 * wr00);
    const float RWz0 = fmaf(R01, wr11, R00 * wr10);
    const float RWz1 = fmaf(R11, wr11, R10 * wr10);
    const float RWz2 = fmaf(R21, wr11, R20 * wr10);
    const float RWn0 = fmaf(R01, wr21, R00 * wr20);
    const float RWn1 = fmaf(R11, wr21, R10 * wr20);
    const float RWn2 = fmaf(R21, wr21, R20 * wr20);
    const float cbr = fmaf(br1, wr01, br0 * wr00);
    const float cbz = fmaf(br1, wr11, br0 * wr10);
    const float cbn = fmaf(br1, wr21, br0 * wr20);

    // seed parity-0 buffer with h(3) = 0
    hbuf[w][0][lane] = 0.f;
    h_own = 0.f;
    __syncwarp();

    // 4-deep prefetch: sets A,B,C,D hold gx(t), gx(t+1), gx(t+2), gx(t+3)
    float gA0 = gx0, gA1 = gx1, gA2 = gx2;               // gx(4)
    const __half* q5 = gxp + (size_t)5 * G3;
    float gB0 = __half2float(q5[lane]);
    float gB1 = __half2float(q5[lane + 32]);
    float gB2 = __half2float(q5[lane + 64]);
    const __half* q6 = gxp + (size_t)6 * G3;
    float gC0 = __half2float(q6[lane]);
    float gC1 = __half2float(q6[lane + 32]);
    float gC2 = __half2float(q6[lane + 64]);
    const __half* q7 = gxp + (size_t)7 * G3;
    float gD0 = __half2float(q7[lane]);
    float gD1 = __half2float(q7[lane + 32]);
    float gD2 = __half2float(q7[lane + 64]);

    // ---------- hot loop: t = 4..511, unrolled by 4, 4-deep prefetch ----------
#define HSTEP(PAR, GX0, GX1, GX2, TCUR)                                          \
    {                                                                            \
        const __half* q = gxp + (size_t)(((TCUR) + 4 < SS) ? (TCUR) + 4 : SS - 1) * G3; \
        float n0 = __half2float(q[lane]);                                        \
        float n1 = __half2float(q[lane + 32]);                                   \
        float n2 = __half2float(q[lane + 64]);                                   \
        const ulonglong2* hbv = (const ulonglong2*)hbuf[w][PAR];                 \
        ull arA = 0, azA = 0, anA = 0, arB = 0, azB = 0, anB = 0, as_ = 0;       \
        _Pragma("unroll")                                                        \
        for (int k2 = 0; k2 < 8; ++k2) {                                         \
            ulonglong2 hp2 = hbv[k2];                                            \
            ffma2(arA, hp2.x, whh0[2 * k2]);                                     \
            ffma2(arB, hp2.y, whh0[2 * k2 + 1]);                                 \
            ffma2(azA, hp2.x, whh1[2 * k2]);                                     \
            ffma2(azB, hp2.y, whh1[2 * k2 + 1]);                                 \
            ffma2(anA, hp2.x, whh2s[2 * k2][lane]);                              \
            ffma2(anB, hp2.y, whh2s[2 * k2 + 1][lane]);                          \
            if (lane < 3) {                                                      \
                ulonglong2 av = As2[w][k2][lane];                                \
                ffma2(as_, hp2.x, av.x);                                         \
                ffma2(as_, hp2.y, av.y);                                         \
            }                                                                    \
        }                                                                        \
        float s_l = hsum(as_) + cA;                                              \
        float s0 = __shfl_sync(0xffffffffu, s_l, 0);                             \
        float s1 = __shfl_sync(0xffffffffu, s_l, 1);                             \
        float s2 = __shfl_sync(0xffffffffu, s_l, 2);                             \
        float p0 = __expf(s0), p1 = __expf(s1), p2 = __expf(s2);                 \
        float inv = __fdividef(1.f, p0 + p1 + p2);                               \
        float dr = fmaf(p2, RWr2, fmaf(p1, RWr1, p0 * RWr0));                    \
        float dz = fmaf(p2, RWz2, fmaf(p1, RWz1, p0 * RWz0));                    \
        float dn = fmaf(p2, RWn2, fmaf(p1, RWn1, p0 * RWn0));                    \
        float gxr = fmaf(inv, dr, GX0 + cbr);                                    \
        float gxz = fmaf(inv, dz, GX1 + cbz);                                    \
        float gxn = fmaf(inv, dn, GX2 + cbn);                                    \
        float ghr = hsum(arA) + hsum(arB) + bh0;                                 \
        float ghz = hsum(azA) + hsum(azB) + bh1;                                 \
        float ghn = hsum(anA) + hsum(anB) + bh2;                                 \
        float r = sigmoidf_(gxr + ghr);                                          \
        float z = sigmoidf_(gxz + ghz);                                          \
        float n = tanhf_(fmaf(r, ghn, gxn));                                     \
        float h_new = fmaf(z, h_own - n, n);                                     \
        hrow[(size_t)(TCUR) * HID] = h_new;                                      \
        hbuf[w][(PAR) ^ 1][lane] = h_new;                                        \
        __syncwarp();                                                            \
        h_own = h_new;                                                           \
        GX0 = n0; GX1 = n1; GX2 = n2;                                            \
    }

    for (int t = 4; t < SS; t += 4) {
        HSTEP(0, gA0, gA1, gA2, t)
        HSTEP(1, gB0, gB1, gB2, t + 1)
        HSTEP(0, gC0, gC1, gC2, t + 2)
        HSTEP(1, gD0, gD1, gD2, t + 3)
    }
#undef HSTEP
}

// ============================================================================
// Phase 3 (r13 version): outputs = hiddens @ W_out.T + b_out.
// Warp = 2 rows x 16 outputs; W_out rows in regs; h rows via smem LDS.128.
// ============================================================================
__global__ __launch_bounds__(256) void phase3_kernel(
    const float* __restrict__ hid,
    const float* __restrict__ W_out,
    const float* __restrict__ b_out,
    float* __restrict__ out)
{
    __shared__ __align__(16) float hs[256 * 36];

    const int tid = threadIdx.x;
    const int w = tid >> 5, lane = tid & 31;
    const int j = lane & 15;
    const int half = lane >> 4;

    ull wreg[16];
#pragma unroll
    for (int k = 0; k < 16; ++k)
        wreg[k] = pack2(W_out[j * 32 + 2 * k], W_out[j * 32 + 2 * k + 1]);
    const float bj = b_out[j];

    const size_t base = (size_t)blockIdx.x * 256;
    const float4* src = (const float4*)(hid + base * 32);
    for (int idx = tid; idx < 2048; idx += 256) {
        float4 v = src[idx];
        int r = idx >> 3, c4 = (idx & 7) * 4;
        float* d = hs + r * 36 + c4;
        d[0] = v.x; d[1] = v.y; d[2] = v.z; d[3] = v.w;
    }
    __syncthreads();

    const int row0 = w * 32;
#pragma unroll 4
    for (int i = 0; i < 16; ++i) {
        const int r = row0 + 2 * i + half;
        const ulonglong2* hr2 = (const ulonglong2*)(hs + r * 36);
        ull acc = 0;
#pragma unroll
        for (int k2 = 0; k2 < 8; ++k2) {
            ulonglong2 hv = hr2[k2];
            ffma2(acc, hv.x, wreg[2 * k2]);
            ffma2(acc, hv.y, wreg[2 * k2 + 1]);
        }
        out[(base + r) * 16 + j] = hsum(acc) + bj;
    }
}

// ============================================================================
extern "C" void kernel_launch(void* const* d_in, const int* in_sizes, int n_in,
                              void* d_out, int out_size) {
    const float* inputs   = (const float*)d_in[0];
    const float* w_ih     = (const float*)d_in[1];
    const float* w_hh     = (const float*)d_in[2];
    const float* b_ih     = (const float*)d_in[3];
    const float* b_hh     = (const float*)d_in[4];
    const float* W_key    = (const float*)d_in[5];
    const float* b_key    = (const float*)d_in[6];
    const float* W_query  = (const float*)d_in[7];
    const float* b_query  = (const float*)d_in[8];
    const float* W_value  = (const float*)d_in[9];
    const float* b_value  = (const float*)d_in[10];
    const float* W_recall = (const float*)d_in[11];
    const float* b_recall = (const float*)d_in[12];
    const float* W_out    = (const float*)d_in[13];
    const float* b_out    = (const float*)d_in[14];

    float* out = (float*)d_out;                              // (B,S,16)
    float* hid = (float*)d_out + (size_t)BB * SS * 16;       // (B,S,32)

    precompute_kernel<<<1, 1024>>>(W_key, b_key, W_query, b_query,
                                   W_value, b_value, W_recall);
    phase1_kernel<<<4096, 128>>>(inputs, w_ih, b_ih);
    phase2_kernel<<<512, 128>>>(w_ih, w_hh, b_hh, b_recall, hid);
    phase3_kernel<<<4096, 256>>>(hid, W_out, b_out, out);
}

// round 17
// speedup vs baseline: 1.2725x; 1.2725x over previous
#include <cuda_runtime.h>
#include <cuda_fp16.h>
#include <cstdint>

typedef unsigned long long ull;

#define BB 2048
#define SS 512
#define NROW (BB * SS)
#define G3 96
#define HID 32
#define INSZ 64

// -------- device scratch --------
__device__ __half g_gx[(size_t)NROW * G3];  // fp16 input-part gates (+b_ih), 201MB
__device__ ull    g_Gp[16 * 32];
__device__ float  g_d[32];
__device__ float  g_gv[32];
__device__ float  g_f[1];
__device__ float  g_H[32 * 2];
__device__ float  g_e[2];

// -------- helpers --------
__device__ __forceinline__ void ffma2(ull& d, ull a, ull b) {
    asm("fma.rn.f32x2 %0, %1, %2, %0;" : "+l"(d) : "l"(a), "l"(b));
}
__device__ __forceinline__ ull pack2(float a, float b) {
    ull r; asm("mov.b64 %0, {%1, %2};" : "=l"(r) : "f"(a), "f"(b)); return r;
}
__device__ __forceinline__ float hsum(ull v) {
    return __uint_as_float((unsigned)v) + __uint_as_float((unsigned)(v >> 32));
}
__device__ __forceinline__ float wsum(float v) {
#pragma unroll
    for (int o = 16; o; o >>= 1) v += __shfl_xor_sync(0xffffffffu, v, o);
    return v;
}
__device__ __forceinline__ float sigmoidf_(float x) {
    return __fdividef(1.f, 1.f + __expf(-x));
}
__device__ __forceinline__ float tanhf_(float x) {
    return 1.f - __fdividef(2.f, __expf(2.f * x) + 1.f);
}

// ============================================================================
// Phase 0: precompute folded memory matrices
// ============================================================================
__global__ void precompute_kernel(
    const float* __restrict__ Wk, const float* __restrict__ bk,
    const float* __restrict__ Wq, const float* __restrict__ bq,
    const float* __restrict__ Wv, const float* __restrict__ bv,
    const float* __restrict__ Wr)
{
    __shared__ float Gs[32 * 32];
    int tid = threadIdx.x;
    {
        int i = tid >> 5, j = tid & 31;
        float s = 0.f;
        for (int k = 0; k < 64; ++k) s += Wk[k * 32 + i] * Wq[k * 32 + j];
        Gs[i * 32 + j] = s;
    }
    if (tid < 32) {
        float dv = 0.f, gv = 0.f;
        for (int k = 0; k < 64; ++k) {
            dv += bk[k] * Wq[k * 32 + tid];
            gv += Wk[k * 32 + tid] * bq[k];
        }
        g_d[tid] = dv; g_gv[tid] = gv;
    }
    if (tid == 0) {
        float f = 0.f;
        for (int k = 0; k < 64; ++k) f += bk[k] * bq[k];
        g_f[0] = f;
    }
    if (tid < 64) {
        int i = tid >> 1, r = tid & 1;
        float s = 0.f;
        for (int v = 0; v < 64; ++v) s += Wv[v * 32 + i] * Wr[r * 64 + v];
        g_H[i * 2 + r] = s;
    }
    if (tid < 2) {
        float s = 0.f;
        for (int v = 0; v < 64; ++v) s += bv[v] * Wr[tid * 64 + v];
        g_e[tid] = s;
    }
    __syncthreads();
    if (tid < 512) {
        int k = tid >> 5, j = tid & 31;
        g_Gp[tid] = pack2(Gs[(2 * k) * 32 + j], Gs[(2 * k + 1) * 32 + j]);
    }
}

// ============================================================================
// Phase 1: GX[row][96] = inputs[row][0:64] @ w_ih[:, :64].T + b_ih  (fp16 out)
// ============================================================================
__global__ __launch_bounds__(128) void phase1_kernel(
    const float* __restrict__ xin,
    const float* __restrict__ w_ih,
    const float* __restrict__ b_ih)
{
    __shared__ __align__(16) ulonglong2 w4s[16 * 96];
    __shared__ __align__(16) ulonglong2 xb[4][128];

    const int tid = threadIdx.x;
    const int w = tid >> 5, lane = tid & 31;

    for (int idx = tid; idx < 16 * 96; idx += 128) {
        int kq = idx / 96, j = idx % 96;
        const float* p = w_ih + j * 66 + kq * 4;
        ulonglong2 v; v.x = pack2(p[0], p[1]); v.y = pack2(p[2], p[3]);
        w4s[idx] = v;
    }
    const float b0 = b_ih[lane], b1 = b_ih[lane + 32], b2 = b_ih[lane + 64];
    __syncthreads();

    const int blockRow0 = blockIdx.x * 256;
    for (int tile = 0; tile < 8; ++tile) {
        const int rowBase = blockRow0 + tile * 32 + w * 8;
        const ulonglong2* src = (const ulonglong2*)(xin + (size_t)rowBase * INSZ);
        __syncwarp();
#pragma unroll
        for (int i = 0; i < 4; ++i) xb[w][lane + 32 * i] = src[lane + 32 * i];
        __syncwarp();

        ull acc[8][3];
#pragma unroll
        for (int r = 0; r < 8; ++r) { acc[r][0] = 0; acc[r][1] = 0; acc[r][2] = 0; }

#pragma unroll
        for (int kq = 0; kq < 16; ++kq) {
            ulonglong2 w0 = w4s[kq * 96 + lane];
            ulonglong2 w1 = w4s[kq * 96 + lane + 32];
            ulonglong2 w2 = w4s[kq * 96 + lane + 64];
#pragma unroll
            for (int r = 0; r < 8; ++r) {
                ulonglong2 xv = xb[w][r * 16 + kq];
                ffma2(acc[r][0], xv.x, w0.x); ffma2(acc[r][0], xv.y, w0.y);
                ffma2(acc[r][1], xv.x, w1.x); ffma2(acc[r][1], xv.y, w1.y);
                ffma2(acc[r][2], xv.x, w2.x); ffma2(acc[r][2], xv.y, w2.y);
            }
        }
#pragma unroll
        for (int r = 0; r < 8; ++r) {
            __half* o = g_gx + (size_t)(rowBase + r) * G3;
            o[lane]      = __float2half_rn(hsum(acc[r][0]) + b0);
            o[lane + 32] = __float2half_rn(hsum(acc[r][1]) + b1);
            o[lane + 64] = __float2half_rn(hsum(acc[r][2]) + b2);
        }
    }
}

// ============================================================================
// Phase 2 (r6 config, fp16 gx): one warp per batch element, lane = hidden idx.
// whh0/1 regs, whh2 smem, 2-deep gx prefetch, parity h-buffers, 15-shfl wsum.
// ============================================================================
__global__ __launch_bounds__(64, 7) void phase2_kernel(
    const float* __restrict__ w_ih,
    const float* __restrict__ w_hh,
    const float* __restrict__ b_hh,
    const float* __restrict__ b_recall,
    float* __restrict__ hid)
{
    __shared__ __align__(16) float hbuf[2][3][32];   // [warp][slot][lane]
    __shared__ __align__(16) ull whh2s[16][33];      // n-gate weights, padded

    const int tid = threadIdx.x;
    const int w = tid >> 5, lane = tid & 31;
    const int b = blockIdx.x * 2 + w;

    for (int idx = tid; idx < 512; idx += 64) {
        int k = idx >> 5, l = idx & 31;
        whh2s[k][l] = pack2(w_hh[(l + 64) * 32 + 2 * k],
                            w_hh[(l + 64) * 32 + 2 * k + 1]);
    }

    ull whh0[16], whh1[16];
    {
        const ulonglong2* p0 = (const ulonglong2*)(w_hh + (size_t)lane * 32);
        const ulonglong2* p1 = (const ulonglong2*)(w_hh + (size_t)(lane + 32) * 32);
#pragma unroll
        for (int i = 0; i < 8; ++i) {
            ulonglong2 v;
            v = p0[i]; whh0[2 * i] = v.x; whh0[2 * i + 1] = v.y;
            v = p1[i]; whh1[2 * i] = v.x; whh1[2 * i + 1] = v.y;
        }
    }
    __syncthreads();

    const float wr00 = w_ih[lane * 66 + 64],        wr01 = w_ih[lane * 66 + 65];
    const float wr10 = w_ih[(lane + 32) * 66 + 64], wr11 = w_ih[(lane + 32) * 66 + 65];
    const float wr20 = w_ih[(lane + 64) * 66 + 64], wr21 = w_ih[(lane + 64) * 66 + 65];
    const float bh0 = b_hh[lane], bh1 = b_hh[lane + 32], bh2 = b_hh[lane + 64];
    const float br0 = b_recall[0], br1 = b_recall[1];

    float A0o = 0.f, A1o = 0.f, A2o = 0.f;
    float c0 = 0.f, c1 = 0.f, c2 = 0.f;
    float R00 = 0.f, R01 = 0.f, R10 = 0.f, R11 = 0.f, R20 = 0.f, R21 = 0.f;
    float retr0 = 0.f, retr1 = 0.f, h_own = 0.f;

    const __half* gxp = g_gx + (size_t)b * SS * G3;
    float* hrow = hid + (size_t)b * SS * HID + lane;
    float gx0 = __half2float(gxp[lane]);
    float gx1 = __half2float(gxp[lane + 32]);
    float gx2 = __half2float(gxp[lane + 64]);
    ull* hb2 = (ull*)hbuf[w][2];

    // ---------- prologue: t = 0..3 ----------
    {
        const float dj = g_d[lane], g_own = g_gv[lane];
        const float H0o = g_H[lane * 2], H1o = g_H[lane * 2 + 1];
        const float fv = g_f[0], e0c = g_e[0], e1c = g_e[1];
#pragma unroll
        for (int t = 0; t < 4; ++t) {
            float gxr = fmaf(retr1, wr01, fmaf(retr0, wr00, gx0));
            float gxz = fmaf(retr1, wr11, fmaf(retr0, wr10, gx1));
            float gxn = fmaf(retr1, wr21, fmaf(retr0, wr20, gx2));
            const __half* q = gxp + (size_t)(t + 1) * G3;
            gx0 = __half2float(q[lane]);
            gx1 = __half2float(q[lane + 32]);
            gx2 = __half2float(q[lane + 64]);

            hbuf[w][2][lane] = h_own; __syncwarp();
            ull ar = 0, az = 0, an = 0;
#pragma unroll
            for (int k = 0; k < 16; ++k) {
                ull hp = hb2[k];
                ffma2(ar, hp, whh0[k]);
                ffma2(az, hp, whh1[k]);
                ffma2(an, hp, whh2s[k][lane]);
            }
            __syncwarp();
            float ghr = hsum(ar) + bh0, ghz = hsum(az) + bh1, ghn = hsum(an) + bh2;
            float r = sigmoidf_(gxr + ghr);
            float z = sigmoidf_(gxz + ghz);
            float n = tanhf_(fmaf(r, ghn, gxn));
            float h_new = (t == 3) ? 0.f : fmaf(z, h_own - n, n);

            if (t < 3) {
                hbuf[w][2][lane] = h_new; __syncwarp();
                ull aa = 0;
#pragma unroll
                for (int k = 0; k < 16; ++k) ffma2(aa, hb2[k], g_Gp[k * 32 + lane]);
                __syncwarp();
                float Av  = hsum(aa) + dj;
                float cv  = wsum(h_new * g_own) + fv;
                float Rv0 = wsum(h_new * H0o) + e0c;
                float Rv1 = wsum(h_new * H1o) + e1c;
                if (t == 0)      { A0o = Av; c0 = cv; R00 = Rv0; R01 = Rv1; }
                else if (t == 1) { A1o = Av; c1 = cv; R10 = Rv0; R11 = Rv1; }
                else             { A2o = Av; c2 = cv; R20 = Rv0; R21 = Rv1; }
            }
            float s0 = wsum(h_new * A0o) + c0;
            float s1 = wsum(h_new * A1o) + c1;
            float s2 = wsum(h_new * A2o) + c2;
            int counter = (t < 3) ? t : 3;
            float m0 = (0 < counter) ? s0 : -1e30f;
            float m1 = (1 < counter) ? s1 : -1e30f;
            float m2 = (2 < counter) ? s2 : -1e30f;
            float p0 = __expf(m0), p1 = __expf(m1), p2 = __expf(m2);
            float inv = __fdividef(1.f, p0 + p1 + p2);
            float nr0 = fmaf(p2, R20, fmaf(p1, R10, p0 * R00)) * inv + br0;
            float nr1 = fmaf(p2, R21, fmaf(p1, R11, p0 * R01)) * inv + br1;
            retr0 = (t > 0) ? nr0 : 0.f;
            retr1 = (t > 0) ? nr1 : 0.f;
            hrow[(size_t)t * HID] = h_new;
            h_own = h_new;
        }
    }

    // seed parity-0 buffer with h(3) = 0; gx(4) in regs; load gx(5)
    hbuf[w][0][lane] = 0.f;
    h_own = 0.f;
    __syncwarp();
    float gA0 = gx0, gA1 = gx1, gA2 = gx2;
    const __half* q5 = gxp + (size_t)5 * G3;
    float gB0 = __half2float(q5[lane]);
    float gB1 = __half2float(q5[lane + 32]);
    float gB2 = __half2float(q5[lane + 64]);

    ull* hbP0 = (ull*)hbuf[w][0];
    ull* hbP1 = (ull*)hbuf[w][1];

    // ---------- hot loop: t = 4..511, unrolled by 2, 2-deep prefetch ----------
#define STEP(PBUF, PARR, GX0, GX1, GX2, TPRE)                                   \
    {                                                                           \
        const __half* q = gxp + (size_t)((TPRE) < SS ? (TPRE) : SS - 1) * G3;   \
        float n0 = __half2float(q[lane]);                                       \
        float n1 = __half2float(q[lane + 32]);                                  \
        float n2 = __half2float(q[lane + 64]);                                  \
        float gxr = fmaf(retr1, wr01, fmaf(retr0, wr00, GX0));                  \
        float gxz = fmaf(retr1, wr11, fmaf(retr0, wr10, GX1));                  \
        float gxn = fmaf(retr1, wr21, fmaf(retr0, wr20, GX2));                  \
        PBUF[lane] = h_own; __syncwarp();                                       \
        ull ar = 0, az = 0, an = 0;                                             \
        _Pragma("unroll")                                                       \
        for (int k = 0; k < 16; ++k) {                                          \
            ull hp = PARR[k];                                                   \
            ffma2(ar, hp, whh0[k]);                                             \
            ffma2(az, hp, whh1[k]);                                             \
            ffma2(an, hp, whh2s[k][lane]);                                      \
        }                                                                       \
        float ghr = hsum(ar) + bh0, ghz = hsum(az) + bh1, ghn = hsum(an) + bh2; \
        float r = sigmoidf_(gxr + ghr);                                         \
        float z = sigmoidf_(gxz + ghz);                                         \
        float n = tanhf_(fmaf(r, ghn, gxn));                                    \
        float h_new = fmaf(z, h_own - n, n);                                    \
        float s0 = wsum(h_new * A0o) + c0;                                      \
        float s1 = wsum(h_new * A1o) + c1;                                      \
        float s2 = wsum(h_new * A2o) + c2;                                      \
        float p0 = __expf(s0), p1 = __expf(s1), p2 = __expf(s2);                \
        float inv = __fdividef(1.f, p0 + p1 + p2);                              \
        retr0 = fmaf(p2, R20, fmaf(p1, R10, p0 * R00)) * inv + br0;             \
        retr1 = fmaf(p2, R21, fmaf(p1, R11, p0 * R01)) * inv + br1;             \
        hrow[(size_t)t_cur * HID] = h_new;                                      \
        h_own = h_new;                                                          \
        GX0 = n0; GX1 = n1; GX2 = n2;                                           \
    }

    for (int t = 4; t < SS; t += 2) {
        {   int t_cur = t;     STEP((&hbuf[w][0][0]), hbP0, gA0, gA1, gA2, t + 2) }
        {   int t_cur = t + 1; STEP((&hbuf[w][1][0]), hbP1, gB0, gB1, gB2, t + 3) }
    }
#undef STEP
}

// ============================================================================
// Phase 3 (r6 version): outputs = hiddens @ W_out.T + b_out.
// Warp = 2 rows x 16 outputs; W_out rows in regs; h staged in padded smem.
// ============================================================================
__global__ __launch_bounds__(256) void phase3_kernel(
    const float* __restrict__ hid,
    const float* __restrict__ W_out,
    const float* __restrict__ b_out,
    float* __restrict__ out)
{
    __shared__ __align__(16) float hs[256 * 36];

    const int tid = threadIdx.x;
    const int w = tid >> 5, lane = tid & 31;
    const int j = lane & 15;
    const int half = lane >> 4;

    ull wreg[16];
#pragma unroll
    for (int k = 0; k < 16; ++k)
        wreg[k] = pack2(W_out[j * 32 + 2 * k], W_out[j * 32 + 2 * k + 1]);
    const float bj = b_out[j];

    const size_t base = (size_t)blockIdx.x * 256;
    const float4* src = (const float4*)(hid + base * 32);
    for (int idx = tid; idx < 2048; idx += 256) {
        float4 v = src[idx];
        int r = idx >> 3, c4 = (idx & 7) * 4;
        float* d = hs + r * 36 + c4;
        d[0] = v.x; d[1] = v.y; d[2] = v.z; d[3] = v.w;
    }
    __syncthreads();

    const int row0 = w * 32;
#pragma unroll 4
    for (int i = 0; i < 16; ++i) {
        const int r = row0 + 2 * i + half;
        const ulonglong2* hr2 = (const ulonglong2*)(hs + r * 36);
        ull acc = 0;
#pragma unroll
        for (int k2 = 0; k2 < 8; ++k2) {
            ulonglong2 hv = hr2[k2];
            ffma2(acc, hv.x, wreg[2 * k2]);
            ffma2(acc, hv.y, wreg[2 * k2 + 1]);
        }
        out[(base + r) * 16 + j] = hsum(acc) + bj;
    }
}

// ============================================================================
extern "C" void kernel_launch(void* const* d_in, const int* in_sizes, int n_in,
                              void* d_out, int out_size) {
    const float* inputs   = (const float*)d_in[0];
    const float* w_ih     = (const float*)d_in[1];
    const float* w_hh     = (const float*)d_in[2];
    const float* b_ih     = (const float*)d_in[3];
    const float* b_hh     = (const float*)d_in[4];
    const float* W_key    = (const float*)d_in[5];
    const float* b_key    = (const float*)d_in[6];
    const float* W_query  = (const float*)d_in[7];
    const float* b_query  = (const float*)d_in[8];
    const float* W_value  = (const float*)d_in[9];
    const float* b_value  = (const float*)d_in[10];
    const float* W_recall = (const float*)d_in[11];
    const float* b_recall = (const float*)d_in[12];
    const float* W_out    = (const float*)d_in[13];
    const float* b_out    = (const float*)d_in[14];

    float* out = (float*)d_out;                              // (B,S,16)
    float* hid = (float*)d_out + (size_t)BB * SS * 16;       // (B,S,32)

    precompute_kernel<<<1, 1024>>>(W_key, b_key, W_query, b_query,
                                   W_value, b_value, W_recall);
    phase1_kernel<<<4096, 128>>>(inputs, w_ih, b_ih);
    phase2_kernel<<<1024, 64>>>(w_ih, w_hh, b_hh, b_recall, hid);
    phase3_kernel<<<4096, 256>>>(hid, W_out, b_out, out);
}